// round 7
// baseline (speedup 1.0000x reference)
#include <cuda_runtime.h>
#include <cuda_bf16.h>

#define EPS 1e-6f

// Packed per-face records: 27 floats used, padded to 32 floats = 128 B
// = exactly 4 L2 sectors, 32B-aligned. Corner-major layout:
//   corner k at offset 9k:  pos(3) nrm(3) col(3)
#define MAX_FACES 204800
__device__ __align__(128) float g_packed[(size_t)MAX_FACES * 32];
// Combined lighting coefficients: kamb(3) kdif(3) kspec(3) shin, pad to 12
__device__ __align__(16) float g_coef[12];

// 256-bit load (Blackwell LDG.E.256): one full 32B sector per lane.
__device__ __forceinline__ void ldg256(const float* __restrict__ p, float* r) {
    asm volatile("ld.global.nc.v8.f32 {%0,%1,%2,%3,%4,%5,%6,%7}, [%8];"
        : "=f"(r[0]), "=f"(r[1]), "=f"(r[2]), "=f"(r[3]),
          "=f"(r[4]), "=f"(r[5]), "=f"(r[6]), "=f"(r[7])
        : "l"(p));
}

__global__ void setup_coef_kernel(
    const float* __restrict__ l_amb,  const float* __restrict__ l_dif,
    const float* __restrict__ l_spec, const float* __restrict__ m_amb,
    const float* __restrict__ m_dif,  const float* __restrict__ m_spec,
    const float* __restrict__ shin)
{
    if (threadIdx.x == 0) {
        #pragma unroll
        for (int c = 0; c < 3; c++) {
            g_coef[0 + c] = m_amb[c]  * l_amb[c];
            g_coef[3 + c] = m_dif[c]  * l_dif[c];
            g_coef[6 + c] = m_spec[c] * l_spec[c];
        }
        g_coef[9]  = shin[0];
        g_coef[10] = 0.0f;
        g_coef[11] = 0.0f;
    }
}

// 3 threads per face: thread t handles corner k = t%3 of face f = t/3.
// faces[t] is a perfectly coalesced load.
__global__ __launch_bounds__(256) void prepack_kernel(
    const int*   __restrict__ faces,
    const float* __restrict__ verts,
    const float* __restrict__ vnorm,
    const float* __restrict__ vcol,
    int F3)
{
    int t = blockIdx.x * blockDim.x + threadIdx.x;
    if (t >= F3) return;
    int f = t / 3;
    int k = t - 3 * f;
    int v = faces[t];

    float* o = g_packed + (size_t)f * 32 + 9 * k;
    o[0] = verts[3*v + 0];
    o[1] = verts[3*v + 1];
    o[2] = verts[3*v + 2];
    o[3] = vnorm[3*v + 0];
    o[4] = vnorm[3*v + 1];
    o[5] = vnorm[3*v + 2];
    o[6] = vcol[3*v + 0];
    o[7] = vcol[3*v + 1];
    o[8] = vcol[3*v + 2];
}

__device__ __forceinline__ void shade_and_store(
    float px, float py, float pz,
    float nx, float ny, float nz,
    float tr, float tg, float tb,
    float lx, float ly, float lz,
    float cx, float cy, float cz,
    const float* kamb, const float* kdif, const float* kspec,
    float sh, float4* outp)
{
    // normalize normal
    {
        float nn  = sqrtf(nx*nx + ny*ny + nz*nz);
        float inv = 1.0f / fmaxf(nn, EPS);
        nx *= inv; ny *= inv; nz *= inv;
    }
    // to_light
    float tlx = lx - px, tly = ly - py, tlz = lz - pz;
    {
        float nn  = sqrtf(tlx*tlx + tly*tly + tlz*tlz);
        float inv = 1.0f / fmaxf(nn, EPS);
        tlx *= inv; tly *= inv; tlz *= inv;
    }
    float cosang = nx*tlx + ny*tly + nz*tlz;
    float dmax   = fmaxf(cosang, 0.0f);

    float spec = 0.0f;
    if (cosang > 0.0f) {
        float vx = cx - px, vy = cy - py, vz = cz - pz;
        float nn  = sqrtf(vx*vx + vy*vy + vz*vz);
        float inv = 1.0f / fmaxf(nn, EPS);
        vx *= inv; vy *= inv; vz *= inv;

        float c2 = 2.0f * cosang;
        float rx = c2*nx - tlx;
        float ry = c2*ny - tly;
        float rz = c2*nz - tlz;

        float alpha = fmaxf(vx*rx + vy*ry + vz*rz, 0.0f);
        if (alpha > 0.0f)
            spec = __powf(alpha, sh);
    }

    float cr = (kamb[0] + kdif[0]*dmax) * tr + kspec[0]*spec;
    float cg = (kamb[1] + kdif[1]*dmax) * tg + kspec[1]*spec;
    float cb = (kamb[2] + kdif[2]*dmax) * tb + kspec[2]*spec;

    *outp = make_float4(cr, cg, cb, 1.0f);
}

// Fast path: 4x 256-bit loads from a single 128B face record.
__global__ __launch_bounds__(256) void shade_packed_kernel(
    const int*   __restrict__ p2f,
    const float* __restrict__ bary,
    const float* __restrict__ lloc,
    const float* __restrict__ cam,
    const float* __restrict__ bg,
    float4*      __restrict__ out,
    int HW)
{
    int pix = blockIdx.x * blockDim.x + threadIdx.x;
    if (pix >= HW) return;
    int nb = blockIdx.y;
    int i  = nb * HW + pix;

    int f = p2f[i];
    if (f < 0) {
        out[i] = make_float4(bg[0], bg[1], bg[2], 0.0f);
        return;
    }

    float b0 = bary[3*i + 0];
    float b1 = bary[3*i + 1];
    float b2 = bary[3*i + 2];

    const float* q = g_packed + (size_t)f * 32;
    float a[32];
    ldg256(q +  0, a +  0);
    ldg256(q +  8, a +  8);
    ldg256(q + 16, a + 16);
    ldg256(q + 24, a + 24);

    // corner-major: corner k at 9k -> pos(3) nrm(3) col(3)
    float px = b0*a[0] + b1*a[ 9] + b2*a[18];
    float py = b0*a[1] + b1*a[10] + b2*a[19];
    float pz = b0*a[2] + b1*a[11] + b2*a[20];

    float nx = b0*a[3] + b1*a[12] + b2*a[21];
    float ny = b0*a[4] + b1*a[13] + b2*a[22];
    float nz = b0*a[5] + b1*a[14] + b2*a[23];

    float tr = b0*a[6] + b1*a[15] + b2*a[24];
    float tg = b0*a[7] + b1*a[16] + b2*a[25];
    float tb = b0*a[8] + b1*a[17] + b2*a[26];

    shade_and_store(px, py, pz, nx, ny, nz, tr, tg, tb,
                    lloc[3*nb+0], lloc[3*nb+1], lloc[3*nb+2],
                    cam[3*nb+0],  cam[3*nb+1],  cam[3*nb+2],
                    g_coef + 0, g_coef + 3, g_coef + 6,
                    g_coef[9], &out[i]);
}

// Fallback path (F > MAX_FACES): direct gathers.
__global__ __launch_bounds__(256) void shade_direct_kernel(
    const int*   __restrict__ p2f,
    const float* __restrict__ bary,
    const float* __restrict__ verts,
    const float* __restrict__ vnorm,
    const float* __restrict__ vcol,
    const int*   __restrict__ faces,
    const float* __restrict__ lloc,
    const float* __restrict__ cam,
    const float* __restrict__ bg,
    float4*      __restrict__ out,
    int HW)
{
    int pix = blockIdx.x * blockDim.x + threadIdx.x;
    if (pix >= HW) return;
    int nb = blockIdx.y;
    int i  = nb * HW + pix;

    int f = p2f[i];
    if (f < 0) {
        out[i] = make_float4(bg[0], bg[1], bg[2], 0.0f);
        return;
    }

    float b0 = bary[3*i + 0];
    float b1 = bary[3*i + 1];
    float b2 = bary[3*i + 2];

    int v0 = faces[3*f + 0];
    int v1 = faces[3*f + 1];
    int v2 = faces[3*f + 2];

    float px = b0*verts[3*v0+0] + b1*verts[3*v1+0] + b2*verts[3*v2+0];
    float py = b0*verts[3*v0+1] + b1*verts[3*v1+1] + b2*verts[3*v2+1];
    float pz = b0*verts[3*v0+2] + b1*verts[3*v1+2] + b2*verts[3*v2+2];

    float nx = b0*vnorm[3*v0+0] + b1*vnorm[3*v1+0] + b2*vnorm[3*v2+0];
    float ny = b0*vnorm[3*v0+1] + b1*vnorm[3*v1+1] + b2*vnorm[3*v2+1];
    float nz = b0*vnorm[3*v0+2] + b1*vnorm[3*v1+2] + b2*vnorm[3*v2+2];

    float tr = b0*vcol[3*v0+0] + b1*vcol[3*v1+0] + b2*vcol[3*v2+0];
    float tg = b0*vcol[3*v0+1] + b1*vcol[3*v1+1] + b2*vcol[3*v2+1];
    float tb = b0*vcol[3*v0+2] + b1*vcol[3*v1+2] + b2*vcol[3*v2+2];

    shade_and_store(px, py, pz, nx, ny, nz, tr, tg, tb,
                    lloc[3*nb+0], lloc[3*nb+1], lloc[3*nb+2],
                    cam[3*nb+0],  cam[3*nb+1],  cam[3*nb+2],
                    g_coef + 0, g_coef + 3, g_coef + 6,
                    g_coef[9], &out[i]);
}

extern "C" void kernel_launch(void* const* d_in, const int* in_sizes, int n_in,
                              void* d_out, int out_size) {
    const int*   p2f    = (const int*)  d_in[0];
    const float* bary   = (const float*)d_in[1];
    const float* verts  = (const float*)d_in[2];
    const float* vnorm  = (const float*)d_in[3];
    const float* vcol   = (const float*)d_in[4];
    const int*   faces  = (const int*)  d_in[5];
    const float* lloc   = (const float*)d_in[6];
    const float* l_amb  = (const float*)d_in[7];
    const float* l_dif  = (const float*)d_in[8];
    const float* l_spec = (const float*)d_in[9];
    const float* m_amb  = (const float*)d_in[10];
    const float* m_dif  = (const float*)d_in[11];
    const float* m_spec = (const float*)d_in[12];
    const float* shin   = (const float*)d_in[13];
    const float* cam    = (const float*)d_in[14];
    const float* bg     = (const float*)d_in[15];

    int total = in_sizes[0];          // N*H*W*K, K=1
    int N     = in_sizes[6] / 3;      // light_location is (N,3)
    int HW    = total / N;
    int F3    = in_sizes[5];          // 3*F
    int F     = F3 / 3;

    int threads = 256;
    dim3 grid((HW + threads - 1) / threads, N);

    setup_coef_kernel<<<1, 32>>>(l_amb, l_dif, l_spec, m_amb, m_dif, m_spec, shin);

    if (F <= MAX_FACES) {
        prepack_kernel<<<(F3 + threads - 1) / threads, threads>>>(
            faces, verts, vnorm, vcol, F3);
        shade_packed_kernel<<<grid, threads>>>(
            p2f, bary, lloc, cam, bg, (float4*)d_out, HW);
    } else {
        shade_direct_kernel<<<grid, threads>>>(
            p2f, bary, verts, vnorm, vcol, faces, lloc, cam, bg,
            (float4*)d_out, HW);
    }
}